// round 13
// baseline (speedup 1.0000x reference)
#include <cuda_runtime.h>

#define NXg 4096
#define NYg 4096
#define JV  (NYg / 4)   // 1024 float4 lanes per row
#define RSTRIP 16       // rows swept per thread (halo amplification 18/16 = 1.125x)
#define TPB 128

// 7 CTAs * 4 warps = 28 warps/SM; grid 2048 -> waves = 2048/1036 = 1.977
// (tail penalty ~1.2%). Reg budget 73 at occ 7 -> no spill expected.
__global__ __launch_bounds__(TPB, 7)
void diffreact_sweep(const float* __restrict__ state,
                     const float* __restrict__ bc,
                     const float* __restrict__ a_p,
                     const float* __restrict__ b_p,
                     const float* __restrict__ k_p,
                     float* __restrict__ out)
{
    const int tid   = blockIdx.x * TPB + threadIdx.x;
    const int strip = tid >> 10;          // JV = 1024 = 2^10
    const int jv    = tid & (JV - 1);
    const int lane  = threadIdx.x & 31;   // warps are row-aligned (TPB % 32 == 0)
    const int i0    = strip * RSTRIP;

    const int plane = NXg * NYg;          // 2^24, fits int
    const float* __restrict__ U = state;
    const float* __restrict__ V = state + plane;
    float* __restrict__ outU = out;
    float* __restrict__ outV = out + plane;

    // params: a,b,k = sigmoid(x)*0.01 ; fold inv_dx2 = 100 into diffusion coeff
    const float a  = 0.01f / (1.0f + __expf(-__ldg(a_p)));
    const float b  = 0.01f / (1.0f + __expf(-__ldg(b_p)));
    const float k  = 0.01f / (1.0f + __expf(-__ldg(k_p)));
    const float ai = a * 100.0f;
    const float bi = b * 100.0f;

    // bc layout: [0,0,:]=U {l,r,t,b}; [0,1,:]=V {l,r,t,b} — loaded lazily in
    // boundary branches (L1 hits) instead of pinned registers.

    int base = i0 * NYg + (jv << 2);      // element offset, < 2^24

    // prime: up-row and current row
    float4 up_u, up_v;
    if (i0 > 0) {
        up_u = *reinterpret_cast<const float4*>(U + (base - NYg));
        up_v = *reinterpret_cast<const float4*>(V + (base - NYg));
    } else {
        const float tU = __ldg(bc + 2), tV = __ldg(bc + 6);
        up_u = make_float4(tU, tU, tU, tU);
        up_v = make_float4(tV, tV, tV, tV);
    }
    float4 cu = *reinterpret_cast<const float4*>(U + base);
    float4 cv = *reinterpret_cast<const float4*>(V + base);

#pragma unroll
    for (int r = 0; r < RSTRIP; ++r) {
        const int i = i0 + r;

        // next (down) row
        float4 dn_u, dn_v;
        if (i < NXg - 1) {
            dn_u = *reinterpret_cast<const float4*>(U + (base + NYg));
            dn_v = *reinterpret_cast<const float4*>(V + (base + NYg));
        } else {
            const float bU = __ldg(bc + 3), bV = __ldg(bc + 7);
            dn_u = make_float4(bU, bU, bU, bU);
            dn_v = make_float4(bV, bV, bV, bV);
        }

        // horizontal halos via warp shuffle; lanes 0/31 patch from gmem / bc
        float ul = __shfl_up_sync(0xffffffffu, cu.w, 1);
        float vl = __shfl_up_sync(0xffffffffu, cv.w, 1);
        float ur = __shfl_down_sync(0xffffffffu, cu.x, 1);
        float vr = __shfl_down_sync(0xffffffffu, cv.x, 1);
        if (lane == 0) {
            ul = (jv > 0) ? __ldg(U + (base - 1)) : __ldg(bc + 0);
            vl = (jv > 0) ? __ldg(V + (base - 1)) : __ldg(bc + 4);
        }
        if (lane == 31) {
            ur = (jv < JV - 1) ? __ldg(U + (base + 4)) : __ldg(bc + 1);
            vr = (jv < JV - 1) ? __ldg(V + (base + 4)) : __ldg(bc + 5);
        }

        // 5-point laplacian sums (inv_dx2 folded into ai/bi)
        float4 lu, lv;
        lu.x = up_u.x + dn_u.x + ul   + cu.y - 4.0f * cu.x;
        lu.y = up_u.y + dn_u.y + cu.x + cu.z - 4.0f * cu.y;
        lu.z = up_u.z + dn_u.z + cu.y + cu.w - 4.0f * cu.z;
        lu.w = up_u.w + dn_u.w + cu.z + ur   - 4.0f * cu.w;

        lv.x = up_v.x + dn_v.x + vl   + cv.y - 4.0f * cv.x;
        lv.y = up_v.y + dn_v.y + cv.x + cv.z - 4.0f * cv.y;
        lv.z = up_v.z + dn_v.z + cv.y + cv.w - 4.0f * cv.z;
        lv.w = up_v.w + dn_v.w + cv.z + vr   - 4.0f * cv.w;

        // dU = a*lapU + U - U^3 - V - k ; dV = b*lapV + U - V
        float4 dU, dV;
        dU.x = fmaf(ai, lu.x, cu.x - cu.x * cu.x * cu.x - cv.x - k);
        dU.y = fmaf(ai, lu.y, cu.y - cu.y * cu.y * cu.y - cv.y - k);
        dU.z = fmaf(ai, lu.z, cu.z - cu.z * cu.z * cu.z - cv.z - k);
        dU.w = fmaf(ai, lu.w, cu.w - cu.w * cu.w * cu.w - cv.w - k);

        dV.x = fmaf(bi, lv.x, cu.x - cv.x);
        dV.y = fmaf(bi, lv.y, cu.y - cv.y);
        dV.z = fmaf(bi, lv.z, cu.z - cv.z);
        dV.w = fmaf(bi, lv.w, cu.w - cv.w);

        // streaming stores: output is never re-read; keep L2 for input reuse
        __stcs(reinterpret_cast<float4*>(outU + base), dU);
        __stcs(reinterpret_cast<float4*>(outV + base), dV);

        // rotate the row window
        up_u = cu; up_v = cv;
        cu = dn_u; cv = dn_v;
        base += NYg;
    }
}

extern "C" void kernel_launch(void* const* d_in, const int* in_sizes, int n_in,
                              void* d_out, int out_size)
{
    const float* state = (const float*)d_in[0];  // (1,2,4096,4096) f32
    const float* bc    = (const float*)d_in[1];  // (1,2,4) f32
    const float* a_p   = (const float*)d_in[2];
    const float* b_p   = (const float*)d_in[3];
    const float* k_p   = (const float*)d_in[4];
    float* out = (float*)d_out;

    const int total_threads = (NXg / RSTRIP) * JV;  // 256 * 1024 = 262144
    const int blocks = total_threads / TPB;         // 2048
    diffreact_sweep<<<blocks, TPB>>>(state, bc, a_p, b_p, k_p, out);
}

// round 14
// speedup vs baseline: 1.1705x; 1.1705x over previous
#include <cuda_runtime.h>

#define NXg 4096
#define NYg 4096
#define JV  (NYg / 4)   // 1024 float4 lanes per row
#define RSTRIP 8        // rows swept per thread (validated sweet spot)
#define TPB 128

// 9 CTAs * 4 warps = 36 warps/SM; grid 4096 -> waves = 4096/(148*9) = 3.074
// (tail penalty ~2.4%). Reg cap at occ 9 = 56; kernel compiles to 55.
__global__ __launch_bounds__(TPB, 9)
void diffreact_sweep(const float* __restrict__ state,
                     const float* __restrict__ bc,
                     const float* __restrict__ a_p,
                     const float* __restrict__ b_p,
                     const float* __restrict__ k_p,
                     float* __restrict__ out)
{
    const int tid   = blockIdx.x * TPB + threadIdx.x;
    const int strip = tid >> 10;          // JV = 1024 = 2^10
    const int jv    = tid & (JV - 1);
    const int lane  = threadIdx.x & 31;   // warps are row-aligned (TPB % 32 == 0)
    const int i0    = strip * RSTRIP;

    const int plane = NXg * NYg;          // 2^24, fits int
    const float* __restrict__ U = state;
    const float* __restrict__ V = state + plane;
    float* __restrict__ outU = out;
    float* __restrict__ outV = out + plane;

    // params: a,b,k = sigmoid(x)*0.01 ; fold inv_dx2 = 100 into diffusion coeff
    const float a  = 0.01f / (1.0f + __expf(-__ldg(a_p)));
    const float b  = 0.01f / (1.0f + __expf(-__ldg(b_p)));
    const float k  = 0.01f / (1.0f + __expf(-__ldg(k_p)));
    const float ai = a * 100.0f;
    const float bi = b * 100.0f;

    // bc layout: [0,0,:]=U {l,r,t,b}; [0,1,:]=V {l,r,t,b} — loaded lazily in
    // boundary branches (L1 hits) instead of pinned registers.

    int base = i0 * NYg + (jv << 2);      // element offset, < 2^24

    // prime: up-row and current row
    float4 up_u, up_v;
    if (i0 > 0) {
        up_u = *reinterpret_cast<const float4*>(U + (base - NYg));
        up_v = *reinterpret_cast<const float4*>(V + (base - NYg));
    } else {
        const float tU = __ldg(bc + 2), tV = __ldg(bc + 6);
        up_u = make_float4(tU, tU, tU, tU);
        up_v = make_float4(tV, tV, tV, tV);
    }
    float4 cu = *reinterpret_cast<const float4*>(U + base);
    float4 cv = *reinterpret_cast<const float4*>(V + base);

#pragma unroll
    for (int r = 0; r < RSTRIP; ++r) {
        const int i = i0 + r;

        // next (down) row
        float4 dn_u, dn_v;
        if (i < NXg - 1) {
            dn_u = *reinterpret_cast<const float4*>(U + (base + NYg));
            dn_v = *reinterpret_cast<const float4*>(V + (base + NYg));
        } else {
            const float bU = __ldg(bc + 3), bV = __ldg(bc + 7);
            dn_u = make_float4(bU, bU, bU, bU);
            dn_v = make_float4(bV, bV, bV, bV);
        }

        // horizontal halos via warp shuffle; lanes 0/31 patch from gmem / bc
        float ul = __shfl_up_sync(0xffffffffu, cu.w, 1);
        float vl = __shfl_up_sync(0xffffffffu, cv.w, 1);
        float ur = __shfl_down_sync(0xffffffffu, cu.x, 1);
        float vr = __shfl_down_sync(0xffffffffu, cv.x, 1);
        if (lane == 0) {
            ul = (jv > 0) ? __ldg(U + (base - 1)) : __ldg(bc + 0);
            vl = (jv > 0) ? __ldg(V + (base - 1)) : __ldg(bc + 4);
        }
        if (lane == 31) {
            ur = (jv < JV - 1) ? __ldg(U + (base + 4)) : __ldg(bc + 1);
            vr = (jv < JV - 1) ? __ldg(V + (base + 4)) : __ldg(bc + 5);
        }

        // 5-point laplacian sums (inv_dx2 folded into ai/bi)
        float4 lu, lv;
        lu.x = up_u.x + dn_u.x + ul   + cu.y - 4.0f * cu.x;
        lu.y = up_u.y + dn_u.y + cu.x + cu.z - 4.0f * cu.y;
        lu.z = up_u.z + dn_u.z + cu.y + cu.w - 4.0f * cu.z;
        lu.w = up_u.w + dn_u.w + cu.z + ur   - 4.0f * cu.w;

        lv.x = up_v.x + dn_v.x + vl   + cv.y - 4.0f * cv.x;
        lv.y = up_v.y + dn_v.y + cv.x + cv.z - 4.0f * cv.y;
        lv.z = up_v.z + dn_v.z + cv.y + cv.w - 4.0f * cv.z;
        lv.w = up_v.w + dn_v.w + cv.z + vr   - 4.0f * cv.w;

        // dU = a*lapU + U - U^3 - V - k ; dV = b*lapV + U - V
        float4 dU, dV;
        dU.x = fmaf(ai, lu.x, cu.x - cu.x * cu.x * cu.x - cv.x - k);
        dU.y = fmaf(ai, lu.y, cu.y - cu.y * cu.y * cu.y - cv.y - k);
        dU.z = fmaf(ai, lu.z, cu.z - cu.z * cu.z * cu.z - cv.z - k);
        dU.w = fmaf(ai, lu.w, cu.w - cu.w * cu.w * cu.w - cv.w - k);

        dV.x = fmaf(bi, lv.x, cu.x - cv.x);
        dV.y = fmaf(bi, lv.y, cu.y - cv.y);
        dV.z = fmaf(bi, lv.z, cu.z - cv.z);
        dV.w = fmaf(bi, lv.w, cu.w - cv.w);

        // streaming stores: output is never re-read; keep L2 for input reuse
        __stcs(reinterpret_cast<float4*>(outU + base), dU);
        __stcs(reinterpret_cast<float4*>(outV + base), dV);

        // rotate the row window
        up_u = cu; up_v = cv;
        cu = dn_u; cv = dn_v;
        base += NYg;
    }
}

extern "C" void kernel_launch(void* const* d_in, const int* in_sizes, int n_in,
                              void* d_out, int out_size)
{
    const float* state = (const float*)d_in[0];  // (1,2,4096,4096) f32
    const float* bc    = (const float*)d_in[1];  // (1,2,4) f32
    const float* a_p   = (const float*)d_in[2];
    const float* b_p   = (const float*)d_in[3];
    const float* k_p   = (const float*)d_in[4];
    float* out = (float*)d_out;

    const int total_threads = (NXg / RSTRIP) * JV;  // 524288
    const int blocks = total_threads / TPB;         // 4096
    diffreact_sweep<<<blocks, TPB>>>(state, bc, a_p, b_p, k_p, out);
}